// round 6
// baseline (speedup 1.0000x reference)
#include <cuda_runtime.h>

// FullNet_29008209117719: tau[N,48,9] = a[n,j] * T[ch,j]
//   T[ch,j] = exp(w_lin[j,ch]) * (j<2 ? 1 : FILT[j-2,ch])   (constant per launch)
//   a[n,0]=c[n,0]; a[n,1]=c[n,1]; a[n,2+g]=c[n,2+g]*sigmoid(MLP_g(t_p[n]))
// Store-bound: 453 MB output. Single-wave config: 128-thr blocks, <=32 regs,
// ~10KB smem => 16 CTA/SM, grid 2048 fully resident (148*16=2368). Flat
// per-warp traversal: every warp store is a 512B, 128B-aligned STG.128 burst.
// Per-sample scalars in a 12-float wraparound row (a[k%9]) so any phase
// q=(4i)%9 reads 4 consecutive scalars.

#define NTH 128
#define NS  128            // samples per block (1 per thread)
#define ROW 432            // 48 channels * 9 species
#define NF4 (ROW / 4)      // 108 float4 per sample row
#define WCHUNK 3456        // f4s per warp = 32 samples * 108
#define NW  497            // total weight floats staged in smem

__device__ __constant__ unsigned char d_F16[7][16] = {
    {1,1,1,1,1,1,1,1,1,1,1,1,1,0,1,1},  // h2o
    {0,0,0,1,1,0,1,1,0,0,0,0,1,0,0,0},  // o3
    {0,0,1,1,1,1,1,1,0,0,0,1,1,1,1,0},  // co2
    {1,0,0,0,0,0,0,0,0,0,1,0,0,0,0,0},  // o2
    {0,0,1,0,0,0,0,1,1,0,0,0,1,0,1,0},  // n2o
    {0,0,0,0,0,0,0,0,1,0,0,0,0,0,0,1},  // ch4
    {0,0,0,0,0,0,0,1,0,0,0,0,1,0,0,0},  // co
};

// smem weight layout offsets
#define OFF_W1 0      // 7*6*2 = 84
#define OFF_B1 84     // 7*6   = 42
#define OFF_W2 126    // 7*4*6 = 168
#define OFF_B2 294    // 7*4   = 28
#define OFF_W3 322    // 7*4*4 = 112
#define OFF_B3 434    // 7*4   = 28
#define OFF_WO 462    // 7*4   = 28
#define OFF_BO 490    // 7     = 7   -> 497 total

__global__ __launch_bounds__(NTH, 16) void fullnet_kernel(
    const float* __restrict__ t_p,   // [N,2]
    const float* __restrict__ c,     // [N,9]
    const float* __restrict__ w_lin, // [9,48]
    const float* __restrict__ W1, const float* __restrict__ b1,
    const float* __restrict__ W2, const float* __restrict__ b2,
    const float* __restrict__ W3, const float* __restrict__ b3,
    const float* __restrict__ Wo, const float* __restrict__ bo,
    float* __restrict__ out,         // [N,48,9]
    int Ntot)
{
    __shared__ float4 sT4[NF4];        // T table as 108 float4
    __shared__ float  sa12[NS][12];    // wraparound scalars: sa12[n][k]=a[n][k%9]
    __shared__ float  sw[NW];          // all MLP weights

    const int tid  = threadIdx.x;
    const int lane = tid & 31;
    const int warp = tid >> 5;

    // ---- stage weights into smem ----
    for (int i = tid; i < NW; i += NTH) {
        float v;
        if      (i < OFF_B1) v = W1[i - OFF_W1];
        else if (i < OFF_W2) v = b1[i - OFF_B1];
        else if (i < OFF_B2) v = W2[i - OFF_W2];
        else if (i < OFF_W3) v = b2[i - OFF_B2];
        else if (i < OFF_B3) v = W3[i - OFF_W3];
        else if (i < OFF_WO) v = b3[i - OFF_B3];
        else if (i < OFF_BO) v = Wo[i - OFF_WO];
        else                 v = bo[i - OFF_BO];
        sw[i] = v;
    }

    // ---- build constant table T ----
    float* sTf = (float*)sT4;
    for (int k = tid; k < ROW; k += NTH) {
        int ch = k / 9, j = k % 9;
        float m = (j < 2) ? 1.0f : (float)d_F16[j - 2][ch / 3];
        sTf[k] = m * expf(w_lin[j * 48 + ch]);
    }

    // ---- per-sample loads straight into smem (keeps regs low) ----
    const int n = blockIdx.x * NS + tid;
    float tt = 0.f, pp = 0.f;
    if (n < Ntot) {
        tt = t_p[2 * n];
        pp = t_p[2 * n + 1];
        #pragma unroll
        for (int j = 0; j < 9; j++) sa12[tid][j] = c[9 * n + j];
    } else {
        #pragma unroll
        for (int j = 0; j < 9; j++) sa12[tid][j] = 0.f;
    }
    sa12[tid][9]  = sa12[tid][0];
    sa12[tid][10] = sa12[tid][1];

    __syncthreads();  // sw + sT staged

    // ---- MLPs (one sample per thread); sa12[2+g] *= sigmoid(ke) ----
    #pragma unroll 1
    for (int g = 0; g < 7; g++) {
        const float* w1 = &sw[OFF_W1 + g * 12];
        const float* B1 = &sw[OFF_B1 + g * 6];
        float h1[6];
        #pragma unroll
        for (int h = 0; h < 6; h++) {
            float v = fmaf(w1[2 * h], tt, fmaf(w1[2 * h + 1], pp, B1[h]));
            h1[h] = v > 0.f ? v : 0.f;
        }
        const float* w2 = &sw[OFF_W2 + g * 24];
        const float* B2 = &sw[OFF_B2 + g * 4];
        float h2[4];
        #pragma unroll
        for (int o = 0; o < 4; o++) {
            float v = B2[o];
            #pragma unroll
            for (int h = 0; h < 6; h++) v = fmaf(w2[o * 6 + h], h1[h], v);
            h2[o] = v > 0.f ? v : 0.f;
        }
        const float* w3 = &sw[OFF_W3 + g * 16];
        const float* B3 = &sw[OFF_B3 + g * 4];
        float h3[4];
        #pragma unroll
        for (int o = 0; o < 4; o++) {
            float v = B3[o];
            #pragma unroll
            for (int h = 0; h < 4; h++) v = fmaf(w3[o * 4 + h], h2[h], v);
            h3[o] = v > 0.f ? v : 0.f;
        }
        float v = sw[OFF_BO + g];
        #pragma unroll
        for (int h = 0; h < 4; h++) v = fmaf(sw[OFF_WO + g * 4 + h], h3[h], v);
        float ke = 1.0f / (1.0f + __expf(-v));
        float ag = sa12[tid][2 + g] * ke;   // own row: no sync needed
        sa12[tid][2 + g] = ag;
        if (g == 0) sa12[tid][11] = ag;     // mirror slot for a[2]
    }

    __syncwarp();  // warp w's flat chunk covers exactly its own samples [32w,32w+32)

    // ---- flat warp-owned write phase (all stores 128B-aligned full lines) ----
    // f4 index i = warp*3456 + it*32 + lane. Phase q = (4i) mod 9 is globally
    // consistent (row length 432 == 0 mod 9). Per iter: i+=32 -> q+=2 (mod 9).
    const long long gbase = (long long)blockIdx.x * NS;
    if (gbase + NS <= Ntot) {
        int r = lane;                        // f4 index within current sample row
        int q = (4 * lane) % 9;              // scalar phase (3456 == 0 mod 9)
        const float* pa = &sa12[warp * 32][0];
        float* po = out + (size_t)gbase * ROW + (size_t)4 * (warp * WCHUNK + lane);

        #pragma unroll 4
        for (int it = 0; it < 108; it++) {
            float4 t4 = sT4[r];
            float a0 = pa[q];
            float a1 = pa[q + 1];
            float a2 = pa[q + 2];
            float a3 = pa[q + 3];
            float4 o;
            o.x = a0 * t4.x;
            o.y = a1 * t4.y;
            o.z = a2 * t4.z;
            o.w = a3 * t4.w;
            __stcs((float4*)po, o);
            po += 128;                       // 32 f4 = 128 floats per warp-iter
            q += 2; if (q >= 9) q -= 9;      // (4*32) mod 9 = 2
            r += 32; if (r >= NF4) { r -= NF4; pa += 12; }
        }
    } else {
        // tail path (bounds-checked, generic)
        const float* sTs = (const float*)sT4;
        for (int i = warp * WCHUNK + lane; i < (warp + 1) * WCHUNK; i += 32) {
            int nl = i / NF4;
            if (gbase + nl >= Ntot) break;
            int k = (i - nl * NF4) * 4;
            int q = (4 * i) % 9;
            const float* pa = &sa12[nl][0];
            float4 o;
            o.x = pa[q]     * sTs[k];
            o.y = pa[q + 1] * sTs[k + 1];
            o.z = pa[q + 2] * sTs[k + 2];
            o.w = pa[q + 3] * sTs[k + 3];
            *(float4*)(out + (size_t)gbase * ROW + (size_t)4 * i) = o;
        }
    }
}

extern "C" void kernel_launch(void* const* d_in, const int* in_sizes, int n_in,
                              void* d_out, int out_size)
{
    const float* t_p   = (const float*)d_in[0];
    const float* c     = (const float*)d_in[1];
    const float* w_lin = (const float*)d_in[2];
    const float* W1    = (const float*)d_in[3];
    const float* b1    = (const float*)d_in[4];
    const float* W2    = (const float*)d_in[5];
    const float* b2    = (const float*)d_in[6];
    const float* W3    = (const float*)d_in[7];
    const float* b3    = (const float*)d_in[8];
    const float* Wo    = (const float*)d_in[9];
    const float* bo    = (const float*)d_in[10];
    float* out = (float*)d_out;

    int Ntot = in_sizes[1] / 9;   // c is [N,9]
    int nblk = (Ntot + NS - 1) / NS;
    fullnet_kernel<<<nblk, NTH>>>(t_p, c, w_lin, W1, b1, W2, b2, W3, b3, Wo, bo,
                                  out, Ntot);
}